// round 5
// baseline (speedup 1.0000x reference)
#include <cuda_runtime.h>
#include <math.h>

typedef unsigned long long ull;

#define SEQ   1024
#define BATCH 64
#define DIN   256
#define HID   512
#define BUN   512

// ---------------- device scratch (no allocation allowed) ----------------
// Xp layout: [t][g][j][r]  (g = batch group 0..7, r = row-in-group 0..7)
__device__ __align__(16) float g_Xp[(size_t)SEQ * 8 * 512 * 8];   // 128 MB
__device__ __align__(16) float g_H[8 * 512 * 8];                  // [g][j][r]
__device__ __align__(16) float g_Z[8 * 512 * 8];                  // [g][j][r]
__device__ unsigned g_ctr[256];                                   // 1 counter / group, 128B apart

// ---------------- packed f32x2 helpers ----------------
__device__ __forceinline__ ull ffma2(ull a, ull b, ull c) {
    ull d; asm("fma.rn.f32x2 %0, %1, %2, %3;" : "=l"(d) : "l"(a), "l"(b), "l"(c)); return d;
}
__device__ __forceinline__ ull add2(ull a, ull b) {
    ull d; asm("add.rn.f32x2 %0, %1, %2;" : "=l"(d) : "l"(a), "l"(b)); return d;
}
__device__ __forceinline__ ull pack2(float x, float y) {
    ull d; asm("mov.b64 %0, {%1, %2};" : "=l"(d) : "f"(x), "f"(y)); return d;
}
__device__ __forceinline__ float2 unpack2(ull a) {
    float2 r; asm("mov.b64 {%0, %1}, %2;" : "=f"(r.x), "=f"(r.y) : "l"(a)); return r;
}

// ---------------- L1-bypassing global access ----------------
__device__ __forceinline__ float4 ldcg4(const float* p) {
    float4 v;
    asm volatile("ld.global.cg.v4.f32 {%0,%1,%2,%3}, [%4];"
                 : "=f"(v.x), "=f"(v.y), "=f"(v.z), "=f"(v.w) : "l"(p));
    return v;
}
__device__ __forceinline__ ull ldcg8(const float* p) {
    ull v; asm volatile("ld.global.cg.u64 %0, [%1];" : "=l"(v) : "l"(p)); return v;
}
__device__ __forceinline__ void stcg8(float* p, ull v) {
    asm volatile("st.global.cg.u64 [%0], %1;" :: "l"(p), "l"(v));
}

// ---------------- init: zero H and barrier counters (every replay) ------
__global__ void __launch_bounds__(256) init_kernel() {
    int t = threadIdx.x;
    g_ctr[t] = 0u;
    for (int i = t; i < 8 * 512 * 8; i += 256) g_H[i] = 0.0f;
}

// ---------------------------------------------------------------------------
// Precompute: Xp[t][g][j][r] = X[b][t][:256] @ Wb[0:256][j] + bb[j], b = 8g+r
// grid (8 col-blocks of 64, 1024 seq), 256 threads, block tile 64x64, K=256.
// ---------------------------------------------------------------------------
__global__ void __launch_bounds__(256) pre_kernel(const float* __restrict__ X,
                                                  const float* __restrict__ Wb,
                                                  const float* __restrict__ bb) {
    __shared__ float AsmT[64 * 64];   // [k][b]  16 KB
    __shared__ float Bsm[64 * 64];    // [k][j]  16 KB

    const int tid = threadIdx.x;
    const int tx  = tid & 15;         // cols 4tx..4tx+3
    const int ty  = tid >> 4;         // rows 4ty..4ty+3
    const int s   = blockIdx.y;
    const int jb  = blockIdx.x * 64;

    ull acc[8];                        // [rowpair(2)][col(4)]
#pragma unroll
    for (int i = 0; i < 8; i++) acc[i] = 0ull;

    for (int kt = 0; kt < 4; kt++) {
        const int kg = kt * 64;
        // stage A transposed: AsmT[k][b] = X[b][s][kg+k]
#pragma unroll
        for (int i = 0; i < 4; i++) {
            int v = tid + 256 * i;     // 0..1023
            int k = v & 63;
            int bg = v >> 6;           // 0..15 (4 batch rows each)
            float4 a;
            a.x = __ldg(&X[(size_t)(4 * bg + 0) * SEQ * DIN + (size_t)s * DIN + kg + k]);
            a.y = __ldg(&X[(size_t)(4 * bg + 1) * SEQ * DIN + (size_t)s * DIN + kg + k]);
            a.z = __ldg(&X[(size_t)(4 * bg + 2) * SEQ * DIN + (size_t)s * DIN + kg + k]);
            a.w = __ldg(&X[(size_t)(4 * bg + 3) * SEQ * DIN + (size_t)s * DIN + kg + k]);
            *(float4*)&AsmT[k * 64 + 4 * bg] = a;
        }
        // stage B: Bsm[k][j] = Wb[kg+k][jb+j]
#pragma unroll
        for (int i = 0; i < 4; i++) {
            int v = tid + 256 * i;
            int k = v >> 4;
            int q = v & 15;
            *(float4*)&Bsm[k * 64 + 4 * q] =
                __ldg((const float4*)&Wb[(size_t)(kg + k) * BUN + jb + 4 * q]);
        }
        __syncthreads();
#pragma unroll 8
        for (int k = 0; k < 64; k++) {
            float4 w = *(const float4*)&Bsm[k * 64 + 4 * tx];
            ulonglong2 a = *(const ulonglong2*)&AsmT[k * 64 + 4 * ty];
            ull w0 = pack2(w.x, w.x), w1 = pack2(w.y, w.y);
            ull w2 = pack2(w.z, w.z), w3 = pack2(w.w, w.w);
            acc[0] = ffma2(a.x, w0, acc[0]);
            acc[1] = ffma2(a.x, w1, acc[1]);
            acc[2] = ffma2(a.x, w2, acc[2]);
            acc[3] = ffma2(a.x, w3, acc[3]);
            acc[4] = ffma2(a.y, w0, acc[4]);
            acc[5] = ffma2(a.y, w1, acc[5]);
            acc[6] = ffma2(a.y, w2, acc[6]);
            acc[7] = ffma2(a.y, w3, acc[7]);
        }
        __syncthreads();
    }

    const int b0 = 4 * ty;
    const int g  = b0 >> 3;
    const int r  = b0 & 7;
#pragma unroll
    for (int cc = 0; cc < 4; cc++) {
        int j = jb + 4 * tx + cc;
        float bias = __ldg(&bb[j]);
        float2 p0 = unpack2(acc[cc]);
        float2 p1 = unpack2(acc[4 + cc]);
        float4 o = make_float4(p0.x + bias, p0.y + bias, p1.x + bias, p1.y + bias);
        *(float4*)&g_Xp[(((size_t)s * 8 + g) * 512 + j) * 8 + r] = o;
    }
}

// ---------------------------------------------------------------------------
// Persistent recurrent kernel: 128 CTAs = 8 groups x 16 col-blocks.
// ---------------------------------------------------------------------------
#define WBH_F 16384          // 512 x 32
#define WH_F  16384
#define SCR_F 8704           // max(HT = 4352 f, RED = 128*34 ull = 8704 f)
#define SMEM_BYTES ((WBH_F + WH_F + SCR_F) * 4)
#define RED_STRIDE 34        // ull stride, 16B-aligned per row, conflict-free reads

// 16-iteration k-slice inner loop (fma-pipe bound)
__device__ __forceinline__ void kloop(const float* __restrict__ wp,
                                      const float* __restrict__ hp,
                                      ull* __restrict__ acc) {
#pragma unroll
    for (int i = 0; i < 16; i++) {
        float4 w = *(const float4*)(wp + 32 * i);
        ulonglong2 hA = *(const ulonglong2*)(hp + 8 * i);
        ulonglong2 hB = *(const ulonglong2*)(hp + 8 * i + 4);
        ull w0 = pack2(w.x, w.x), w1 = pack2(w.y, w.y);
        ull w2 = pack2(w.z, w.z), w3 = pack2(w.w, w.w);
        acc[0]  = ffma2(hA.x, w0, acc[0]);
        acc[1]  = ffma2(hA.x, w1, acc[1]);
        acc[2]  = ffma2(hA.x, w2, acc[2]);
        acc[3]  = ffma2(hA.x, w3, acc[3]);
        acc[4]  = ffma2(hA.y, w0, acc[4]);
        acc[5]  = ffma2(hA.y, w1, acc[5]);
        acc[6]  = ffma2(hA.y, w2, acc[6]);
        acc[7]  = ffma2(hA.y, w3, acc[7]);
        acc[8]  = ffma2(hB.x, w0, acc[8]);
        acc[9]  = ffma2(hB.x, w1, acc[9]);
        acc[10] = ffma2(hB.x, w2, acc[10]);
        acc[11] = ffma2(hB.x, w3, acc[11]);
        acc[12] = ffma2(hB.y, w0, acc[12]);
        acc[13] = ffma2(hB.y, w1, acc[13]);
        acc[14] = ffma2(hB.y, w2, acc[14]);
        acc[15] = ffma2(hB.y, w3, acc[15]);
    }
}

// Producer-side arrival: caller has already issued its global stores.
// fence(release) -> warp sync -> one relaxed RED per warp.
__device__ __forceinline__ void warp_arrive(unsigned* ctr, int lane) {
    asm volatile("fence.acq_rel.gpu;" ::: "memory");
    __syncwarp();
    if (lane == 0)
        asm volatile("red.relaxed.gpu.global.add.u32 [%0], %1;" :: "l"(ctr), "r"(1u) : "memory");
}

// Consumer-side wait: thread 0 relaxed-polls, acquire fence, block barrier.
__device__ __forceinline__ void group_wait(unsigned* ctr, unsigned target, int tid) {
    if (tid == 0) {
        unsigned v;
        do {
            asm volatile("ld.relaxed.gpu.global.u32 %0, [%1];" : "=r"(v) : "l"(ctr) : "memory");
        } while (v < target);
        asm volatile("fence.acq_rel.gpu;" ::: "memory");
    }
    __syncthreads();
}

__global__ void __launch_bounds__(256, 1) rec_kernel(const float* __restrict__ Wb,
                                                     const float* __restrict__ Wh,
                                                     const float* __restrict__ bh,
                                                     const float* __restrict__ tau,
                                                     float* __restrict__ out) {
    extern __shared__ float smem[];
    float* WBHs = smem;                 // [k][32] cols j0..j0+31 of Wb[256:]
    float* WHs  = smem + WBH_F;         // [k][32] cols of Wh
    float* SCR  = smem + WBH_F + WH_F;  // HT (staged operand) / RED (partials)

    const int tid  = threadIdx.x;
    const int lane = tid & 31;
    const int g    = blockIdx.x >> 4;   // batch group
    const int cb   = blockIdx.x & 15;   // column block
    const int j0   = cb * 32;
    const int cg   = tid & 7;           // column sub-group (4 cols)
    const int ks   = tid >> 3;          // k-slice 0..31 (16 k each)
    const int c0   = 4 * cg;

    // --- preload weight slices into smem (held for all 1024 steps) ---
#pragma unroll
    for (int i = 0; i < 16; i++) {
        int v = tid + 256 * i;          // 0..4095 float4-slots
        int row = v >> 3;               // 0..511
        int q = v & 7;
        *(float4*)&WBHs[row * 32 + 4 * q] =
            __ldg((const float4*)&Wb[(size_t)(256 + row) * BUN + j0 + 4 * q]);
        *(float4*)&WHs[row * 32 + 4 * q] =
            __ldg((const float4*)&Wh[(size_t)row * HID + j0 + 4 * q]);
    }

    // --- hoisted epilogue state (output-owning threads: tid < 128) ---
    float ebh = 0.0f, ertau = 0.0f;
    ull h_reg = 0ull;
    const float* xpp = g_Xp;
    float *gzp = g_Z, *ghp = g_H, *o0 = out, *o1 = out;
    if (tid < 128) {
        int erp = tid >> 5;             // row pair (rows 2erp, 2erp+1)
        int ec = tid & 31;
        int ej = j0 + ec;
        ebh = __ldg(&bh[ej]);
        ertau = 1.0f / __ldg(&tau[ej]);
        xpp = g_Xp + ((size_t)g * 512 + ej) * 8 + 2 * erp;
        gzp = g_Z + (size_t)g * 4096 + ej * 8 + 2 * erp;
        ghp = g_H + (size_t)g * 4096 + ej * 8 + 2 * erp;
        int b0 = g * 8 + 2 * erp;
        o0 = out + ((size_t)b0 * SEQ) * HID + ej;
        o1 = out + ((size_t)(b0 + 1) * SEQ) * HID + ej;
    }

    const float* gHbase = g_H + (size_t)g * 4096;
    const float* gZbase = g_Z + (size_t)g * 4096;
    unsigned* ctr = &g_ctr[g * 32];
    unsigned bt = 0;
    ull* RED = (ull*)SCR;
    const float* wbh_p = WBHs + ks * 512 + c0;
    const float* wh_p  = WHs + ks * 512 + c0;
    const float* ht_p  = SCR + ks * 136;

    __syncthreads();                    // weights staged

    for (int t = 0; t < SEQ; t++) {
        // prefetch this step's Xp (DRAM) off the critical path
        ull xpv = 0ull;
        if (tid < 128) {
            xpv = ldcg8(xpp);
            if (t + 1 < SEQ)
                asm volatile("prefetch.global.L2 [%0];" :: "l"(xpp + 8 * 4096));
        }

        // ================= GEMM1: z = h @ Wbh (+ Xp) =================
        // stage h into skewed transposed layout HT[(k>>4)*136 + (k&15)*8 + r]
#pragma unroll
        for (int i = 0; i < 4; i++) {
            int v = tid + 256 * i;      // float4-slot over [j][r] = 4096 floats
            float4 d = ldcg4(gHbase + 4 * v);
            int k = v >> 1, half = v & 1;
            *(float4*)&SCR[(k >> 4) * 136 + (k & 15) * 8 + 4 * half] = d;
        }
        __syncthreads();
        {
            ull acc[16];
#pragma unroll
            for (int i = 0; i < 16; i++) acc[i] = 0ull;
            kloop(wbh_p, ht_p, acc);
            __syncthreads();            // done reading HT before RED overwrite
#pragma unroll
            for (int rp = 0; rp < 4; rp++)
#pragma unroll
                for (int cj = 0; cj < 4; cj++)
                    RED[(rp * 32 + c0 + cj) * RED_STRIDE + ks] = acc[rp * 4 + cj];
        }
        __syncthreads();
        bt += 64;
        if (tid < 128) {
            const ull* rb = RED + tid * RED_STRIDE;
            ulonglong2 p = *(const ulonglong2*)rb;
            ulonglong2 q = *(const ulonglong2*)(rb + 2);
            ull s0 = p.x, s1 = p.y, s2 = q.x, s3 = q.y;
#pragma unroll
            for (int i = 2; i < 16; i += 2) {
                ulonglong2 a = *(const ulonglong2*)(rb + 2 * i);
                ulonglong2 b = *(const ulonglong2*)(rb + 2 * i + 2);
                s0 = add2(s0, a.x); s1 = add2(s1, a.y);
                s2 = add2(s2, b.x); s3 = add2(s3, b.y);
            }
            ull z2 = add2(add2(s0, s1), add2(s2, s3));
            z2 = add2(z2, xpv);
            stcg8(gzp, z2);
            xpp += 8 * 4096;            // next t
            warp_arrive(ctr, lane);     // release z, arrive (per producer warp)
        }
        group_wait(ctr, bt, tid);

        // ================= GEMM2: d = tanh(z @ Wh + bh) =================
#pragma unroll
        for (int i = 0; i < 4; i++) {
            int v = tid + 256 * i;
            float4 d = ldcg4(gZbase + 4 * v);
            int k = v >> 1, half = v & 1;
            *(float4*)&SCR[(k >> 4) * 136 + (k & 15) * 8 + 4 * half] = d;
        }
        __syncthreads();
        {
            ull acc[16];
#pragma unroll
            for (int i = 0; i < 16; i++) acc[i] = 0ull;
            kloop(wh_p, ht_p, acc);
            __syncthreads();
#pragma unroll
            for (int rp = 0; rp < 4; rp++)
#pragma unroll
                for (int cj = 0; cj < 4; cj++)
                    RED[(rp * 32 + c0 + cj) * RED_STRIDE + ks] = acc[rp * 4 + cj];
        }
        __syncthreads();
        bt += 64;
        float hn0 = 0.0f, hn1 = 0.0f;
        if (tid < 128) {
            const ull* rb = RED + tid * RED_STRIDE;
            ulonglong2 p = *(const ulonglong2*)rb;
            ulonglong2 q = *(const ulonglong2*)(rb + 2);
            ull s0 = p.x, s1 = p.y, s2 = q.x, s3 = q.y;
#pragma unroll
            for (int i = 2; i < 16; i += 2) {
                ulonglong2 a = *(const ulonglong2*)(rb + 2 * i);
                ulonglong2 b = *(const ulonglong2*)(rb + 2 * i + 2);
                s0 = add2(s0, a.x); s1 = add2(s1, a.y);
                s2 = add2(s2, b.x); s3 = add2(s3, b.y);
            }
            float2 z = unpack2(add2(add2(s0, s1), add2(s2, s3)));
            float d0 = tanhf(z.x + ebh);
            float d1 = tanhf(z.y + ebh);
            float2 h = unpack2(h_reg);
            hn0 = h.x + (d0 - h.x) * ertau;
            hn1 = h.y + (d1 - h.y) * ertau;
            h_reg = pack2(hn0, hn1);
            stcg8(ghp, h_reg);
            warp_arrive(ctr, lane);     // release h, arrive
            // out stores after arrival: off the fence drain set, nobody reads them
            o0[(size_t)t * HID] = hn0;
            o1[(size_t)t * HID] = hn1;
        }
        group_wait(ctr, bt, tid);
    }
}

// ---------------------------------------------------------------------------
extern "C" void kernel_launch(void* const* d_in, const int* in_sizes, int n_in,
                              void* d_out, int out_size) {
    (void)in_sizes; (void)n_in; (void)out_size;
    const float* X   = (const float*)d_in[0];
    const float* Wb  = (const float*)d_in[1];
    const float* bb  = (const float*)d_in[2];
    const float* Wh  = (const float*)d_in[3];
    const float* bh  = (const float*)d_in[4];
    const float* tau = (const float*)d_in[5];
    float* out = (float*)d_out;

    cudaFuncSetAttribute(rec_kernel, cudaFuncAttributeMaxDynamicSharedMemorySize, SMEM_BYTES);

    init_kernel<<<1, 256>>>();
    dim3 pg(8, SEQ);
    pre_kernel<<<pg, 256>>>(X, Wb, bb);
    rec_kernel<<<128, 256, SMEM_BYTES>>>(Wb, Wh, bh, tau, out);
}

// round 7
// speedup vs baseline: 2.0086x; 2.0086x over previous
#include <cuda_runtime.h>
#include <math.h>

typedef unsigned long long ull;

#define SEQ   1024
#define BATCH 64
#define DIN   256
#define HID   512
#define BUN   512

// ---------------- device scratch (no allocation allowed) ----------------
// g_C layout: [t][g][j][r]  (g = batch group 0..7, r = row-in-group 0..7)
// holds C_t = x_t @ (Wbx@Wh) + (bb@Wh + bh)
__device__ __align__(16) float g_C[(size_t)SEQ * 8 * 512 * 8];    // 128 MB
__device__ __align__(16) float g_H[8 * 512 * 8];                  // [g][j][r]
__device__ __align__(16) float g_P[768 * 512];                    // P = Wb @ Wh (N=rows 0..255, M=rows 256..767)
__device__ __align__(16) float g_c0[512];                         // bb@Wh + bh
__device__ unsigned g_ctr[256];                                   // 1 counter / group, 128B apart

// ---------------- packed f32x2 helpers ----------------
__device__ __forceinline__ ull ffma2(ull a, ull b, ull c) {
    ull d; asm("fma.rn.f32x2 %0, %1, %2, %3;" : "=l"(d) : "l"(a), "l"(b), "l"(c)); return d;
}
__device__ __forceinline__ ull add2(ull a, ull b) {
    ull d; asm("add.rn.f32x2 %0, %1, %2;" : "=l"(d) : "l"(a), "l"(b)); return d;
}
__device__ __forceinline__ ull pack2(float x, float y) {
    ull d; asm("mov.b64 %0, {%1, %2};" : "=l"(d) : "f"(x), "f"(y)); return d;
}
__device__ __forceinline__ float2 unpack2(ull a) {
    float2 r; asm("mov.b64 {%0, %1}, %2;" : "=f"(r.x), "=f"(r.y) : "l"(a)); return r;
}

// ---------------- L1-bypassing global access ----------------
__device__ __forceinline__ float4 ldcg4(const float* p) {
    float4 v;
    asm volatile("ld.global.cg.v4.f32 {%0,%1,%2,%3}, [%4];"
                 : "=f"(v.x), "=f"(v.y), "=f"(v.z), "=f"(v.w) : "l"(p));
    return v;
}
__device__ __forceinline__ ull ldcg8(const float* p) {
    ull v; asm volatile("ld.global.cg.u64 %0, [%1];" : "=l"(v) : "l"(p)); return v;
}
__device__ __forceinline__ void stcg8(float* p, ull v) {
    asm volatile("st.global.cg.u64 [%0], %1;" :: "l"(p), "l"(v));
}

// ---------------- init: zero H and barrier counters (every replay) ------
__global__ void __launch_bounds__(256) init_kernel() {
    int t = threadIdx.x;
    g_ctr[t] = 0u;
    for (int i = t; i < 8 * 512 * 8; i += 256) g_H[i] = 0.0f;
}

// ---------------------------------------------------------------------------
// c0[u] = sum_j bb[j] * Wh[j][u] + bh[u]
// ---------------------------------------------------------------------------
__global__ void __launch_bounds__(512) c0_kernel(const float* __restrict__ bb,
                                                 const float* __restrict__ Wh,
                                                 const float* __restrict__ bh) {
    int u = threadIdx.x;
    float s = __ldg(&bh[u]);
#pragma unroll 8
    for (int j = 0; j < BUN; j++)
        s += __ldg(&bb[j]) * __ldg(&Wh[(size_t)j * HID + u]);
    g_c0[u] = s;
}

// ---------------------------------------------------------------------------
// P = Wb @ Wh   (768 x 512, K = 512). grid (8 colblk, 12 rowblk), 256 thr.
// ---------------------------------------------------------------------------
__global__ void __launch_bounds__(256) pmat_kernel(const float* __restrict__ Wb,
                                                   const float* __restrict__ Wh) {
    __shared__ float Asm[64 * 32];   // [r][k]
    __shared__ float Bsm[32 * 64];   // [k][j]
    const int tid = threadIdx.x;
    const int tx  = tid & 15;        // cols 4tx..4tx+3
    const int ty  = tid >> 4;        // rows 4ty..4ty+3
    const int jb  = blockIdx.x * 64;
    const int rb  = blockIdx.y * 64;

    float acc[16];
#pragma unroll
    for (int i = 0; i < 16; i++) acc[i] = 0.0f;

    for (int kt = 0; kt < 16; kt++) {
        const int kg = kt * 32;
#pragma unroll
        for (int i = 0; i < 2; i++) {
            int v = tid + 256 * i;   // 512 float4-slots
            int r = v >> 3, q = v & 7;
            *(float4*)&Asm[r * 32 + 4 * q] =
                __ldg((const float4*)&Wb[(size_t)(rb + r) * BUN + kg + 4 * q]);
        }
#pragma unroll
        for (int i = 0; i < 2; i++) {
            int v = tid + 256 * i;
            int kk = v >> 4, q = v & 15;
            *(float4*)&Bsm[kk * 64 + 4 * q] =
                __ldg((const float4*)&Wh[(size_t)(kg + kk) * HID + jb + 4 * q]);
        }
        __syncthreads();
#pragma unroll 8
        for (int kk = 0; kk < 32; kk++) {
            float4 b = *(const float4*)&Bsm[kk * 64 + 4 * tx];
            float a0 = Asm[(4 * ty + 0) * 32 + kk];
            float a1 = Asm[(4 * ty + 1) * 32 + kk];
            float a2 = Asm[(4 * ty + 2) * 32 + kk];
            float a3 = Asm[(4 * ty + 3) * 32 + kk];
            acc[0]  += a0 * b.x; acc[1]  += a0 * b.y; acc[2]  += a0 * b.z; acc[3]  += a0 * b.w;
            acc[4]  += a1 * b.x; acc[5]  += a1 * b.y; acc[6]  += a1 * b.z; acc[7]  += a1 * b.w;
            acc[8]  += a2 * b.x; acc[9]  += a2 * b.y; acc[10] += a2 * b.z; acc[11] += a2 * b.w;
            acc[12] += a3 * b.x; acc[13] += a3 * b.y; acc[14] += a3 * b.z; acc[15] += a3 * b.w;
        }
        __syncthreads();
    }
#pragma unroll
    for (int i = 0; i < 4; i++) {
        float4 o = make_float4(acc[4 * i], acc[4 * i + 1], acc[4 * i + 2], acc[4 * i + 3]);
        *(float4*)&g_P[(size_t)(rb + 4 * ty + i) * 512 + jb + 4 * tx] = o;
    }
}

// ---------------------------------------------------------------------------
// Precompute: C[t][g][j][r] = X[b][t][:256] @ N[.][j] + c0[j], b = 8g+r
// N = g_P rows 0..255. grid (8 col-blocks of 64, 1024 seq), 256 threads.
// ---------------------------------------------------------------------------
__global__ void __launch_bounds__(256) pre_kernel(const float* __restrict__ X) {
    __shared__ float AsmT[64 * 64];   // [k][b]
    __shared__ float Bsm[64 * 64];    // [k][j]

    const int tid = threadIdx.x;
    const int tx  = tid & 15;
    const int ty  = tid >> 4;
    const int s   = blockIdx.y;
    const int jb  = blockIdx.x * 64;

    ull acc[8];
#pragma unroll
    for (int i = 0; i < 8; i++) acc[i] = 0ull;

    for (int kt = 0; kt < 4; kt++) {
        const int kg = kt * 64;
#pragma unroll
        for (int i = 0; i < 4; i++) {
            int v = tid + 256 * i;     // 0..1023
            int k = v & 63;
            int bg = v >> 6;           // 0..15 (4 batch rows each)
            float4 a;
            a.x = __ldg(&X[(size_t)(4 * bg + 0) * SEQ * DIN + (size_t)s * DIN + kg + k]);
            a.y = __ldg(&X[(size_t)(4 * bg + 1) * SEQ * DIN + (size_t)s * DIN + kg + k]);
            a.z = __ldg(&X[(size_t)(4 * bg + 2) * SEQ * DIN + (size_t)s * DIN + kg + k]);
            a.w = __ldg(&X[(size_t)(4 * bg + 3) * SEQ * DIN + (size_t)s * DIN + kg + k]);
            *(float4*)&AsmT[k * 64 + 4 * bg] = a;
        }
#pragma unroll
        for (int i = 0; i < 4; i++) {
            int v = tid + 256 * i;
            int k = v >> 4;
            int q = v & 15;
            *(float4*)&Bsm[k * 64 + 4 * q] =
                *(const float4*)&g_P[(size_t)(kg + k) * 512 + jb + 4 * q];
        }
        __syncthreads();
#pragma unroll 8
        for (int k = 0; k < 64; k++) {
            float4 w = *(const float4*)&Bsm[k * 64 + 4 * tx];
            ulonglong2 a = *(const ulonglong2*)&AsmT[k * 64 + 4 * ty];
            ull w0 = pack2(w.x, w.x), w1 = pack2(w.y, w.y);
            ull w2 = pack2(w.z, w.z), w3 = pack2(w.w, w.w);
            acc[0] = ffma2(a.x, w0, acc[0]);
            acc[1] = ffma2(a.x, w1, acc[1]);
            acc[2] = ffma2(a.x, w2, acc[2]);
            acc[3] = ffma2(a.x, w3, acc[3]);
            acc[4] = ffma2(a.y, w0, acc[4]);
            acc[5] = ffma2(a.y, w1, acc[5]);
            acc[6] = ffma2(a.y, w2, acc[6]);
            acc[7] = ffma2(a.y, w3, acc[7]);
        }
        __syncthreads();
    }

    const int b0 = 4 * ty;
    const int g  = b0 >> 3;
    const int r  = b0 & 7;
#pragma unroll
    for (int cc = 0; cc < 4; cc++) {
        int j = jb + 4 * tx + cc;
        float bias = g_c0[j];
        float2 p0 = unpack2(acc[cc]);
        float2 p1 = unpack2(acc[4 + cc]);
        float4 o = make_float4(p0.x + bias, p0.y + bias, p1.x + bias, p1.y + bias);
        *(float4*)&g_C[(((size_t)s * 8 + g) * 512 + j) * 8 + r] = o;
    }
}

// ---------------------------------------------------------------------------
// Persistent recurrent kernel: 128 CTAs = 8 groups x 16 col-blocks.
// Single fused GEMM per step: hn = h + (tanh(h@M + C_t) - h)/tau
// ---------------------------------------------------------------------------
#define M_F   16384          // 512 x 32 (M weight slice)
#define SCR_F 8320           // max(HT = 4352 f, RED = 32*130 ull = 8320 f)
#define SMEM_BYTES ((M_F + SCR_F) * 4)
#define RED_STRIDE 130       // ull stride per k-slice row

__device__ __forceinline__ void kloop(const float* __restrict__ wp,
                                      const float* __restrict__ hp,
                                      ull* __restrict__ acc) {
#pragma unroll
    for (int i = 0; i < 16; i++) {
        float4 w = *(const float4*)(wp + 32 * i);
        ulonglong2 hA = *(const ulonglong2*)(hp + 8 * i);
        ulonglong2 hB = *(const ulonglong2*)(hp + 8 * i + 4);
        ull w0 = pack2(w.x, w.x), w1 = pack2(w.y, w.y);
        ull w2 = pack2(w.z, w.z), w3 = pack2(w.w, w.w);
        acc[0]  = ffma2(hA.x, w0, acc[0]);
        acc[1]  = ffma2(hA.x, w1, acc[1]);
        acc[2]  = ffma2(hA.x, w2, acc[2]);
        acc[3]  = ffma2(hA.x, w3, acc[3]);
        acc[4]  = ffma2(hA.y, w0, acc[4]);
        acc[5]  = ffma2(hA.y, w1, acc[5]);
        acc[6]  = ffma2(hA.y, w2, acc[6]);
        acc[7]  = ffma2(hA.y, w3, acc[7]);
        acc[8]  = ffma2(hB.x, w0, acc[8]);
        acc[9]  = ffma2(hB.x, w1, acc[9]);
        acc[10] = ffma2(hB.x, w2, acc[10]);
        acc[11] = ffma2(hB.x, w3, acc[11]);
        acc[12] = ffma2(hB.y, w0, acc[12]);
        acc[13] = ffma2(hB.y, w1, acc[13]);
        acc[14] = ffma2(hB.y, w2, acc[14]);
        acc[15] = ffma2(hB.y, w3, acc[15]);
    }
}

// R4-proven group barrier: release-add + acquire-spin on an L2 counter
__device__ __forceinline__ void group_bar(unsigned* ctr, unsigned target, int tid) {
    __threadfence();
    __syncthreads();
    if (tid == 0) {
        asm volatile("red.release.gpu.global.add.u32 [%0], %1;" :: "l"(ctr), "r"(1u) : "memory");
        unsigned v;
        do {
            asm volatile("ld.acquire.gpu.global.u32 %0, [%1];" : "=r"(v) : "l"(ctr) : "memory");
        } while (v < target);
    }
    __syncthreads();
}

__global__ void __launch_bounds__(256, 1) rec_kernel(const float* __restrict__ tau,
                                                     float* __restrict__ out) {
    extern __shared__ float smem[];
    float* Ms  = smem;              // [k][32] cols j0..j0+31 of M = P[256:]
    float* SCR = smem + M_F;        // HT (staged operand) / RED (partials)

    const int tid = threadIdx.x;
    const int g   = blockIdx.x >> 4;    // batch group
    const int cb  = blockIdx.x & 15;    // column block
    const int j0  = cb * 32;
    const int cg  = tid & 7;            // column sub-group (4 cols)
    const int ks  = tid >> 3;           // k-slice 0..31 (16 k each)
    const int c0  = 4 * cg;

    // --- preload M slice into smem (held for all 1024 steps) ---
#pragma unroll
    for (int i = 0; i < 16; i++) {
        int v = tid + 256 * i;          // 0..4095 float4-slots
        int row = v >> 3;               // 0..511
        int q = v & 7;
        *(float4*)&Ms[row * 32 + 4 * q] =
            *(const float4*)&g_P[(size_t)(256 + row) * 512 + j0 + 4 * q];
    }

    // --- hoisted epilogue state (output-owning threads: tid < 128) ---
    float ertau = 0.0f;
    ull h_reg = 0ull;
    const float* cpp = g_C;
    float *ghp = g_H, *o0 = out, *o1 = out;
    if (tid < 128) {
        int erp = tid >> 5;             // row pair (rows 2erp, 2erp+1)
        int ec = tid & 31;
        int ej = j0 + ec;
        ertau = 1.0f / __ldg(&tau[ej]);
        cpp = g_C + ((size_t)g * 512 + ej) * 8 + 2 * erp;
        ghp = g_H + (size_t)g * 4096 + ej * 8 + 2 * erp;
        int b0 = g * 8 + 2 * erp;
        o0 = out + ((size_t)b0 * SEQ) * HID + ej;
        o1 = out + ((size_t)(b0 + 1) * SEQ) * HID + ej;
    }

    const float* gHbase = g_H + (size_t)g * 4096;
    unsigned* ctr = &g_ctr[g * 32];
    unsigned bt = 0;
    ull* RED = (ull*)SCR;
    const float* w_p  = Ms + ks * 512 + c0;
    const float* ht_p = SCR + ks * 136;

    __syncthreads();                    // weights staged

    for (int t = 0; t < SEQ; t++) {
        // load this step's C early (DRAM latency hidden under stage+kloop)
        ull cv = 0ull;
        if (tid < 128) cv = ldcg8(cpp);

        // stage h into skewed transposed layout HT[(k>>4)*136 + (k&15)*8 + r]
#pragma unroll
        for (int i = 0; i < 4; i++) {
            int v = tid + 256 * i;      // float4-slot over [j][r] = 4096 floats
            float4 d = ldcg4(gHbase + 4 * v);
            int k = v >> 1, half = v & 1;
            *(float4*)&SCR[(k >> 4) * 136 + (k & 15) * 8 + 4 * half] = d;
        }
        __syncthreads();
        {
            ull acc[16];
#pragma unroll
            for (int i = 0; i < 16; i++) acc[i] = 0ull;
            kloop(w_p, ht_p, acc);
            __syncthreads();            // done reading HT before RED overwrite
#pragma unroll
            for (int rp = 0; rp < 4; rp++) {
                ulonglong2 v0, v1;
                v0.x = acc[rp * 4 + 0]; v0.y = acc[rp * 4 + 1];
                v1.x = acc[rp * 4 + 2]; v1.y = acc[rp * 4 + 3];
                *(ulonglong2*)&RED[ks * RED_STRIDE + rp * 32 + c0]     = v0;
                *(ulonglong2*)&RED[ks * RED_STRIDE + rp * 32 + c0 + 2] = v1;
            }
        }
        __syncthreads();
        if (tid < 128) {
            const ull* rb = RED + tid;      // partial i at rb[i*RED_STRIDE]
            ull s0 = rb[0];
            ull s1 = rb[RED_STRIDE];
            ull s2 = rb[2 * RED_STRIDE];
            ull s3 = rb[3 * RED_STRIDE];
#pragma unroll
            for (int i = 4; i < 32; i += 4) {
                s0 = add2(s0, rb[(i + 0) * RED_STRIDE]);
                s1 = add2(s1, rb[(i + 1) * RED_STRIDE]);
                s2 = add2(s2, rb[(i + 2) * RED_STRIDE]);
                s3 = add2(s3, rb[(i + 3) * RED_STRIDE]);
            }
            float2 z = unpack2(add2(add2(s0, s1), add2(s2, s3)));
            float2 c = unpack2(cv);
            float d0 = tanhf(z.x + c.x);
            float d1 = tanhf(z.y + c.y);
            float2 h = unpack2(h_reg);
            float hn0 = h.x + (d0 - h.x) * ertau;
            float hn1 = h.y + (d1 - h.y) * ertau;
            h_reg = pack2(hn0, hn1);
            stcg8(ghp, h_reg);
            o0[(size_t)t * HID] = hn0;
            o1[(size_t)t * HID] = hn1;
            cpp += 8 * 4096;            // next t
        }
        bt += 16;
        group_bar(ctr, bt, tid);
    }
}

// ---------------------------------------------------------------------------
extern "C" void kernel_launch(void* const* d_in, const int* in_sizes, int n_in,
                              void* d_out, int out_size) {
    (void)in_sizes; (void)n_in; (void)out_size;
    const float* X   = (const float*)d_in[0];
    const float* Wb  = (const float*)d_in[1];
    const float* bb  = (const float*)d_in[2];
    const float* Wh  = (const float*)d_in[3];
    const float* bh  = (const float*)d_in[4];
    const float* tau = (const float*)d_in[5];
    float* out = (float*)d_out;

    cudaFuncSetAttribute(rec_kernel, cudaFuncAttributeMaxDynamicSharedMemorySize, SMEM_BYTES);

    init_kernel<<<1, 256>>>();
    c0_kernel<<<1, 512>>>(bb, Wh, bh);
    dim3 pgrid(8, 12);
    pmat_kernel<<<pgrid, 256>>>(Wb, Wh);
    dim3 cgrid(8, SEQ);
    pre_kernel<<<cgrid, 256>>>(X);
    rec_kernel<<<128, 256, SMEM_BYTES>>>(tau, out);
}